// round 3
// baseline (speedup 1.0000x reference)
#include <cuda_runtime.h>

#define BB     256
#define HH     512
#define CTXL   512
#define PREDL  64
#define KC     16            // K-chunk
#define NCHUNK (HH / HH * 32) // 32 chunks of 16 = 512
#define GRID_X 128
#define NTHR   256

// ---------------- persistent device state (scratch across launches within one call) ------------
__device__ float g_h0[2][HH][BB];   // [buf][k][b]
__device__ float g_h1[2][HH][BB];
__device__ float g_scale[BB];
__device__ float g_inv[BB];

struct __align__(16) Smem {
    float As[2][KC][64];     // A chunk [kk][row], double buffered
    float Bs[2][KC][49];     // B chunk [kk][gate], padded
    float hgA[48][64];       // GEMM result (layer0 hh / layer1 ih)
    float hgB[48][64];       // layer1 hh
    float xv[64];            // per-batch scalar input this step
    float wih0[48];
    float bih0s[48], bhh0s[48], bih1s[48], bhh1s[48];
    float red[8];
};

__device__ __forceinline__ float sigf(float x) {
    return __fdividef(1.0f, 1.0f + __expf(-x));
}
__device__ __forceinline__ float tanh_f(float x) {
    return 2.0f * __fdividef(1.0f, 1.0f + __expf(-2.0f * x)) - 1.0f;
}

// GEMM: hg[c][r] = sum_k A[k][b0+r] * W[gate(c)][k];  c = 48 gates (3 groups of 16), r = 64 rows.
// Asrc already offset by b0: element [k][r] = Asrc[k*BB + r].
__device__ __forceinline__ void gemm_tile(const float* __restrict__ Asrc,
                                          const float* __restrict__ W,
                                          int j0, float (&hg)[48][64], Smem& sm)
{
    const int tid = threadIdx.x;
    const int tr = tid & 15;
    const int tc = tid >> 4;
    const int ar  = tid & 63;
    const int ak0 = tid >> 6;
    const float* ap = Asrc + ak0 * BB + ar;
    const int bk  = tid & 15;
    const int bc0 = tid >> 4;
    const float* wp0 = W + (0 * HH + j0 + bc0) * HH + bk;
    const float* wp1 = W + (1 * HH + j0 + bc0) * HH + bk;
    const float* wp2 = W + (2 * HH + j0 + bc0) * HH + bk;

    float acc[4][3];
#pragma unroll
    for (int i = 0; i < 4; i++)
#pragma unroll
        for (int j = 0; j < 3; j++) acc[i][j] = 0.f;

    float pa[4], pb[3];
#pragma unroll
    for (int q = 0; q < 4; q++) pa[q] = __ldcg(ap + q * 4 * BB);
    pb[0] = __ldg(wp0); pb[1] = __ldg(wp1); pb[2] = __ldg(wp2);
#pragma unroll
    for (int q = 0; q < 4; q++) sm.As[0][ak0 + 4 * q][ar] = pa[q];
    sm.Bs[0][bk][bc0     ] = pb[0];
    sm.Bs[0][bk][bc0 + 16] = pb[1];
    sm.Bs[0][bk][bc0 + 32] = pb[2];
    __syncthreads();

#pragma unroll 2
    for (int kc = 0; kc < 32; ++kc) {
        const int cur = kc & 1;
        if (kc + 1 < 32) {
            const int kb = (kc + 1) * KC;
#pragma unroll
            for (int q = 0; q < 4; q++) pa[q] = __ldcg(ap + (kb + 4 * q) * BB);
            pb[0] = __ldg(wp0 + kb); pb[1] = __ldg(wp1 + kb); pb[2] = __ldg(wp2 + kb);
        }
#pragma unroll
        for (int kk = 0; kk < KC; ++kk) {
            float4 a = *(const float4*)&sm.As[cur][kk][4 * tr];
            float b0v = sm.Bs[cur][kk][3 * tc + 0];
            float b1v = sm.Bs[cur][kk][3 * tc + 1];
            float b2v = sm.Bs[cur][kk][3 * tc + 2];
            acc[0][0] = fmaf(a.x, b0v, acc[0][0]);
            acc[1][0] = fmaf(a.y, b0v, acc[1][0]);
            acc[2][0] = fmaf(a.z, b0v, acc[2][0]);
            acc[3][0] = fmaf(a.w, b0v, acc[3][0]);
            acc[0][1] = fmaf(a.x, b1v, acc[0][1]);
            acc[1][1] = fmaf(a.y, b1v, acc[1][1]);
            acc[2][1] = fmaf(a.z, b1v, acc[2][1]);
            acc[3][1] = fmaf(a.w, b1v, acc[3][1]);
            acc[0][2] = fmaf(a.x, b2v, acc[0][2]);
            acc[1][2] = fmaf(a.y, b2v, acc[1][2]);
            acc[2][2] = fmaf(a.z, b2v, acc[2][2]);
            acc[3][2] = fmaf(a.w, b2v, acc[3][2]);
        }
        if (kc + 1 < 32) {
            const int nxt = cur ^ 1;
#pragma unroll
            for (int q = 0; q < 4; q++) sm.As[nxt][ak0 + 4 * q][ar] = pa[q];
            sm.Bs[nxt][bk][bc0     ] = pb[0];
            sm.Bs[nxt][bk][bc0 + 16] = pb[1];
            sm.Bs[nxt][bk][bc0 + 32] = pb[2];
        }
        __syncthreads();
    }
#pragma unroll
    for (int cc = 0; cc < 3; cc++)
#pragma unroll
        for (int rr = 0; rr < 4; rr++)
            hg[3 * tc + cc][4 * tr + rr] = acc[rr][cc];
}

// layer0 GRU cell: input side is rank-1 (scalar xv per batch), hh GEMM in sm.hgA (raw)
__device__ __forceinline__ void cell0(Smem& sm, int src, int dst, int b0, int j0)
{
    const int tid = threadIdx.x;
#pragma unroll
    for (int q = 0; q < 4; q++) {
        int u = tid + 256 * q;
        int jj = u >> 6, rr = u & 63;
        float xvv = sm.xv[rr];
        float hr = sm.hgA[jj     ][rr] + sm.bhh0s[jj     ];
        float hz = sm.hgA[16 + jj][rr] + sm.bhh0s[16 + jj];
        float hn = sm.hgA[32 + jj][rr] + sm.bhh0s[32 + jj];
        float xr = fmaf(xvv, sm.wih0[jj     ], sm.bih0s[jj     ]);
        float xz = fmaf(xvv, sm.wih0[16 + jj], sm.bih0s[16 + jj]);
        float xn = fmaf(xvv, sm.wih0[32 + jj], sm.bih0s[32 + jj]);
        float r = sigf(xr + hr);
        float z = sigf(xz + hz);
        float n = tanh_f(xn + r * hn);
        float hp = __ldcg(&g_h0[src][j0 + jj][b0 + rr]);
        __stcg(&g_h0[dst][j0 + jj][b0 + rr], (1.f - z) * n + z * hp);
    }
}

// layer1 GRU cell: hgA = y0@Wih1 (raw), hgB = h1@Whh1 (raw); r multiplies only the hh side of n
__device__ __forceinline__ void cell1(Smem& sm, int src, int dst, int b0, int j0)
{
    const int tid = threadIdx.x;
#pragma unroll
    for (int q = 0; q < 4; q++) {
        int u = tid + 256 * q;
        int jj = u >> 6, rr = u & 63;
        float xr = sm.hgA[jj     ][rr] + sm.bih1s[jj     ];
        float xz = sm.hgA[16 + jj][rr] + sm.bih1s[16 + jj];
        float xn = sm.hgA[32 + jj][rr] + sm.bih1s[32 + jj];
        float hr = sm.hgB[jj     ][rr] + sm.bhh1s[jj     ];
        float hz = sm.hgB[16 + jj][rr] + sm.bhh1s[16 + jj];
        float hn = sm.hgB[32 + jj][rr] + sm.bhh1s[32 + jj];
        float r = sigf(xr + hr);
        float z = sigf(xz + hz);
        float n = tanh_f(xn + r * hn);
        float hp = __ldcg(&g_h1[src][j0 + jj][b0 + rr]);
        __stcg(&g_h1[dst][j0 + jj][b0 + rr], (1.f - z) * n + z * hp);
    }
}

// Per-block head over its 64-batch tile: raw[rr] = h1[:, b0+rr] . Wout.
// rr = tid>>2, k-quarter = tid&3 (128 K each), then 4-lane shfl reduce.
__device__ __forceinline__ void head_tile(const float* __restrict__ h1src, int b0,
                                          const float* __restrict__ Wout, float bout0,
                                          Smem& sm)
{
    const int tid = threadIdx.x;
    const int rr = tid >> 2;
    const int kq = tid & 3;
    float s = 0.f;
    const int kbase = kq * 128;
#pragma unroll 4
    for (int i = 0; i < 128; ++i) {
        int k = kbase + i;
        s = fmaf(__ldcg(&h1src[k * BB + b0 + rr]), __ldg(&Wout[k]), s);
    }
    s += __shfl_xor_sync(0xffffffffu, s, 1);
    s += __shfl_xor_sync(0xffffffffu, s, 2);
    if (kq == 0) sm.xv[rr] = s + bout0;   // xv = forecast / scale  (exact)
    __syncthreads();
}

// ---------------- kernel 1: init (zero state buffers, compute scale & 1/scale) -----------------
__global__ void __launch_bounds__(NTHR)
k_init(const float* __restrict__ ctx)
{
    __shared__ float red[8];
    const int tid = threadIdx.x;
    const int bid = blockIdx.x;
    {
        float* z0 = &g_h0[1][0][0];
        float* z1 = &g_h1[0][0][0];
        const int total = HH * BB;
        for (int i = bid * NTHR + tid; i < total; i += GRID_X * NTHR) {
            z0[i] = 0.f;
            z1[i] = 0.f;
        }
    }
    const int b = 2 * bid + (tid >> 7);
    const int t = tid & 127;
    float s = 0.f;
#pragma unroll
    for (int q = 0; q < 4; q++) s += ctx[b * CTXL + t + 128 * q];
#pragma unroll
    for (int o = 16; o; o >>= 1) s += __shfl_xor_sync(0xffffffffu, s, o);
    if ((tid & 31) == 0) red[tid >> 5] = s;
    __syncthreads();
    if ((tid & 127) == 0) {
        int w0 = (tid >> 5);   // 0 or 4
        float m = (red[w0] + red[w0 + 1] + red[w0 + 2] + red[w0 + 3]) * (1.f / CTXL);
        float sc = fmaxf(fabsf(m), 1e-5f);
        g_scale[b] = sc;
        g_inv[b] = __fdividef(1.0f, sc);
    }
}

// ---------------- kernel 2: encoder phase p (layer0 step p + layer1 step p-1) ------------------
__global__ void __launch_bounds__(NTHR)
k_enc(const float* __restrict__ ctx,
      const float* __restrict__ Wih0, const float* __restrict__ Whh0,
      const float* __restrict__ bih0, const float* __restrict__ bhh0,
      const float* __restrict__ Wih1, const float* __restrict__ Whh1,
      const float* __restrict__ bih1, const float* __restrict__ bhh1,
      int p)
{
    __shared__ Smem sm;
    const int tid = threadIdx.x;
    const int bid = blockIdx.x;
    const int b0 = (bid >> 5) * 64;
    const int j0 = (bid & 31) * 16;
    const int src = (p + 1) & 1, dst = p & 1;

    if (tid < 48) {
        int g = (tid >> 4) * HH + j0 + (tid & 15);
        sm.wih0[tid]  = Wih0[g];
        sm.bih0s[tid] = bih0[g];
        sm.bhh0s[tid] = bhh0[g];
        sm.bih1s[tid] = bih1[g];
        sm.bhh1s[tid] = bhh1[g];
    }
    if (p < CTXL && tid < 64)
        sm.xv[tid] = ctx[(b0 + tid) * CTXL + p] * g_inv[b0 + tid];
    __syncthreads();

    if (p < CTXL) {
        gemm_tile(&g_h0[src][0][b0], Whh0, j0, sm.hgA, sm);
        __syncthreads();
        cell0(sm, src, dst, b0, j0);
    }
    if (p >= 1) {
        __syncthreads();
        gemm_tile(&g_h0[src][0][b0], Wih1, j0, sm.hgA, sm);  // input side: y0_{p-1}
        gemm_tile(&g_h1[src][0][b0], Whh1, j0, sm.hgB, sm);  // recurrent side
        __syncthreads();
        cell1(sm, src, dst, b0, j0);
    }
}

// ---------------- kernel 3: decode layer0 (fused head on current h1 -> out[d-1], then cell0) ---
__global__ void __launch_bounds__(NTHR)
k_dec0(const float* __restrict__ Wih0, const float* __restrict__ Whh0,
       const float* __restrict__ bih0, const float* __restrict__ bhh0,
       const float* __restrict__ Wout, const float* __restrict__ bout,
       float* __restrict__ out, int d, int c0, int c1)
{
    __shared__ Smem sm;
    const int tid = threadIdx.x;
    const int bid = blockIdx.x;
    const int b0 = (bid >> 5) * 64;
    const int j0 = (bid & 31) * 16;

    if (tid < 48) {
        int g = (tid >> 4) * HH + j0 + (tid & 15);
        sm.wih0[tid]  = Wih0[g];
        sm.bih0s[tid] = bih0[g];
        sm.bhh0s[tid] = bhh0[g];
    }
    __syncthreads();

    // head on h1[c1] -> sm.xv (= raw + bout = forecast/scale); write forecast d-1
    head_tile(&g_h1[c1][0][0], b0, Wout, __ldg(&bout[0]), sm);
    if (j0 == 0 && (tid & 3) == 0) {
        int rr = tid >> 2;
        out[(b0 + rr) * PREDL + (d - 1)] = sm.xv[rr] * g_scale[b0 + rr];
    }
    __syncthreads();

    gemm_tile(&g_h0[c0][0][b0], Whh0, j0, sm.hgA, sm);
    __syncthreads();
    cell0(sm, c0, c0 ^ 1, b0, j0);
}

// ---------------- kernel 4: decode layer1 ------------------------------------------------------
__global__ void __launch_bounds__(NTHR)
k_dec1(const float* __restrict__ Wih1, const float* __restrict__ Whh1,
       const float* __restrict__ bih1, const float* __restrict__ bhh1,
       int h0buf, int c1)
{
    __shared__ Smem sm;
    const int tid = threadIdx.x;
    const int bid = blockIdx.x;
    const int b0 = (bid >> 5) * 64;
    const int j0 = (bid & 31) * 16;

    if (tid < 48) {
        int g = (tid >> 4) * HH + j0 + (tid & 15);
        sm.bih1s[tid] = bih1[g];
        sm.bhh1s[tid] = bhh1[g];
    }
    __syncthreads();

    gemm_tile(&g_h0[h0buf][0][b0], Wih1, j0, sm.hgA, sm);
    gemm_tile(&g_h1[c1][0][b0], Whh1, j0, sm.hgB, sm);
    __syncthreads();
    cell1(sm, c1, c1 ^ 1, b0, j0);
}

// ---------------- kernel 5: final head (forecast index PRED-1) ---------------------------------
__global__ void __launch_bounds__(NTHR)
k_head(const float* __restrict__ Wout, const float* __restrict__ bout,
       float* __restrict__ out, int c1)
{
    __shared__ Smem sm;
    const int tid = threadIdx.x;
    const int b0 = blockIdx.x * 64;
    head_tile(&g_h1[c1][0][0], b0, Wout, __ldg(&bout[0]), sm);
    if ((tid & 3) == 0) {
        int rr = tid >> 2;
        out[(b0 + rr) * PREDL + (PREDL - 1)] = sm.xv[rr] * g_scale[b0 + rr];
    }
}

extern "C" void kernel_launch(void* const* d_in, const int* in_sizes, int n_in,
                              void* d_out, int out_size)
{
    const float* ctx  = (const float*)d_in[0];
    const float* Wih0 = (const float*)d_in[1];
    const float* Whh0 = (const float*)d_in[2];
    const float* bih0 = (const float*)d_in[3];
    const float* bhh0 = (const float*)d_in[4];
    const float* Wih1 = (const float*)d_in[5];
    const float* Whh1 = (const float*)d_in[6];
    const float* bih1 = (const float*)d_in[7];
    const float* bhh1 = (const float*)d_in[8];
    const float* Wout = (const float*)d_in[9];
    const float* bout = (const float*)d_in[10];
    float* out = (float*)d_out;

    k_init<<<GRID_X, NTHR>>>(ctx);

    // Encoder: 513 skewed phases (layer0 step p, layer1 step p-1)
    for (int p = 0; p <= CTXL; ++p)
        k_enc<<<GRID_X, NTHR>>>(ctx, Wih0, Whh0, bih0, bhh0,
                                Wih1, Whh1, bih1, bhh1, p);

    // After encoder: h0 current buffer = 1, h1 current buffer = 0
    int c0 = 1, c1 = 0;
    for (int d = 1; d < PREDL; ++d) {
        k_dec0<<<GRID_X, NTHR>>>(Wih0, Whh0, bih0, bhh0, Wout, bout, out, d, c0, c1);
        c0 ^= 1;
        k_dec1<<<GRID_X, NTHR>>>(Wih1, Whh1, bih1, bhh1, c0, c1);
        c1 ^= 1;
    }
    k_head<<<4, NTHR>>>(Wout, bout, out, c1);
}

// round 4
// speedup vs baseline: 1.1149x; 1.1149x over previous
#include <cuda_runtime.h>

#define BB     256
#define HH     512
#define CTXL   512
#define PREDL  64
#define KC     16
#define GRID_X 128
#define NTHR   256

typedef unsigned long long u64;
typedef unsigned int u32;

// ---------------- persistent device state (scratch across launches within one call) ------------
__device__ float g_h0[2][HH][BB];   // [buf][k][b]
__device__ float g_h1[2][HH][BB];
__device__ float g_scale[BB];
__device__ float g_inv[BB];

struct __align__(16) Smem {
    float As0[2][KC][64];        // h0 chunk [buf][kk][row]
    float As1[2][KC][64];        // h1 chunk
    float Bs[3][2][KC][49];      // weight chunks [mat][buf][kk][gatecol], padded
    float xv[64];
    float wih0[48];
    float bih0s[48], bhh0s[48], bih1s[48], bhh1s[48];
    float red[8];
};

__device__ __forceinline__ float sigf(float x) {
    return __fdividef(1.0f, 1.0f + __expf(-x));
}
__device__ __forceinline__ float tanh_f(float x) {
    return 2.0f * __fdividef(1.0f, 1.0f + __expf(-2.0f * x)) - 1.0f;
}

// ---------------- f32x2 packed helpers ---------------------------------------------------------
__device__ __forceinline__ void lds_v2u64(u64& lo, u64& hi, u32 addr) {
    asm volatile("ld.shared.v2.u64 {%0, %1}, [%2];" : "=l"(lo), "=l"(hi) : "r"(addr));
}
__device__ __forceinline__ u32 lds_u32(u32 addr) {
    u32 v;
    asm volatile("ld.shared.b32 %0, [%1];" : "=r"(v) : "r"(addr));
    return v;
}
__device__ __forceinline__ u64 pack2(u32 v) {
    u64 r;
    asm("mov.b64 %0, {%1, %1};" : "=l"(r) : "r"(v));
    return r;
}
__device__ __forceinline__ void ffma2(u64& d, u64 a, u64 b) {
    asm("fma.rn.f32x2 %0, %1, %2, %3;" : "=l"(d) : "l"(a), "l"(b), "l"(d));
}
__device__ __forceinline__ void unpack2(float& lo, float& hi, u64 v) {
    u32 l, h;
    asm("mov.b64 {%0, %1}, %2;" : "=r"(l), "=r"(h) : "l"(v));
    lo = __uint_as_float(l);
    hi = __uint_as_float(h);
}

// ---------------- fused triple GEMM ------------------------------------------------------------
// Computes (per thread, rows 4tr..4tr+3, hidden col j=j0+tc, gates {tc,16+tc,32+tc}):
//   D0: acc0 += A0 x W0   (h0 x Whh0)
//   D1: acc1 += A0 x W1   (h0 x Wih1)
//   D2: acc2 += A1 x W2   (h1 x Whh1)
// acc layout: acc[c*2+p], c=gate group (0=r,1=z,2=n), p=row pair (0: rows 0,1; 1: rows 2,3)
template<bool D0, bool D1, bool D2>
__device__ __forceinline__ void fused_gemm(Smem& sm,
                                           const float* __restrict__ A0,
                                           const float* __restrict__ A1,
                                           const float* __restrict__ W0,
                                           const float* __restrict__ W1,
                                           const float* __restrict__ W2,
                                           int j0, u64* acc0, u64* acc1, u64* acc2)
{
    const int tid = threadIdx.x;
    const int tr  = tid & 15;
    const int tc  = tid >> 4;
    const int ar  = tid & 63;
    const int ak0 = tid >> 6;
    const int bk  = tid & 15;
    const int bc0 = tid >> 4;

    const float* ap0 = A0 + ak0 * BB + ar;
    const float* ap1 = A1 + ak0 * BB + ar;
    const float* wB0 = W0 + (j0 + bc0) * HH + bk;
    const float* wB1 = W1 + (j0 + bc0) * HH + bk;
    const float* wB2 = W2 + (j0 + bc0) * HH + bk;

    const u32 as0 = (u32)__cvta_generic_to_shared(&sm.As0[0][0][0]) + tr * 16;
    const u32 as1 = (u32)__cvta_generic_to_shared(&sm.As1[0][0][0]) + tr * 16;
    const u32 bs0 = (u32)__cvta_generic_to_shared(&sm.Bs[0][0][0][0]) + tc * 4;
    const u32 bs1 = (u32)__cvta_generic_to_shared(&sm.Bs[1][0][0][0]) + tc * 4;
    const u32 bs2 = (u32)__cvta_generic_to_shared(&sm.Bs[2][0][0][0]) + tc * 4;

    float pa0[4], pa1[4], pb0[3], pb1[3], pb2[3];

    // prologue: load chunk 0
    if (D0 || D1) {
#pragma unroll
        for (int q = 0; q < 4; q++) pa0[q] = ap0[4 * q * BB];
    }
    if (D2) {
#pragma unroll
        for (int q = 0; q < 4; q++) pa1[q] = ap1[4 * q * BB];
    }
#pragma unroll
    for (int q = 0; q < 3; q++) {
        if (D0) pb0[q] = __ldg(wB0 + q * HH * HH);
        if (D1) pb1[q] = __ldg(wB1 + q * HH * HH);
        if (D2) pb2[q] = __ldg(wB2 + q * HH * HH);
    }
    if (D0 || D1) {
#pragma unroll
        for (int q = 0; q < 4; q++) sm.As0[0][ak0 + 4 * q][ar] = pa0[q];
    }
    if (D2) {
#pragma unroll
        for (int q = 0; q < 4; q++) sm.As1[0][ak0 + 4 * q][ar] = pa1[q];
    }
#pragma unroll
    for (int q = 0; q < 3; q++) {
        if (D0) sm.Bs[0][0][bk][q * 16 + bc0] = pb0[q];
        if (D1) sm.Bs[1][0][bk][q * 16 + bc0] = pb1[q];
        if (D2) sm.Bs[2][0][bk][q * 16 + bc0] = pb2[q];
    }
    __syncthreads();

    for (int kc = 0; kc < 32; ++kc) {
        const int cur = kc & 1;
        if (kc + 1 < 32) {
            const int kb = (kc + 1) * KC;
            if (D0 || D1) {
#pragma unroll
                for (int q = 0; q < 4; q++) pa0[q] = ap0[(kb + 4 * q) * BB];
            }
            if (D2) {
#pragma unroll
                for (int q = 0; q < 4; q++) pa1[q] = ap1[(kb + 4 * q) * BB];
            }
#pragma unroll
            for (int q = 0; q < 3; q++) {
                if (D0) pb0[q] = __ldg(wB0 + q * HH * HH + kb);
                if (D1) pb1[q] = __ldg(wB1 + q * HH * HH + kb);
                if (D2) pb2[q] = __ldg(wB2 + q * HH * HH + kb);
            }
        }
        const u32 a0b = as0 + cur * 4096;
        const u32 a1b = as1 + cur * 4096;
        const u32 b0b = bs0 + cur * 3136;
        const u32 b1b = bs1 + cur * 3136;
        const u32 b2b = bs2 + cur * 3136;
#pragma unroll
        for (int kk = 0; kk < KC; ++kk) {
            u64 a0l = 0, a0h = 0, a1l = 0, a1h = 0;
            if (D0 || D1) lds_v2u64(a0l, a0h, a0b + kk * 256);
            if (D2)       lds_v2u64(a1l, a1h, a1b + kk * 256);
#pragma unroll
            for (int c = 0; c < 3; c++) {
                if (D0) {
                    u64 b = pack2(lds_u32(b0b + kk * 196 + c * 64));
                    ffma2(acc0[c * 2 + 0], a0l, b);
                    ffma2(acc0[c * 2 + 1], a0h, b);
                }
                if (D1) {
                    u64 b = pack2(lds_u32(b1b + kk * 196 + c * 64));
                    ffma2(acc1[c * 2 + 0], a0l, b);
                    ffma2(acc1[c * 2 + 1], a0h, b);
                }
                if (D2) {
                    u64 b = pack2(lds_u32(b2b + kk * 196 + c * 64));
                    ffma2(acc2[c * 2 + 0], a1l, b);
                    ffma2(acc2[c * 2 + 1], a1h, b);
                }
            }
        }
        if (kc + 1 < 32) {
            const int nxt = cur ^ 1;
            if (D0 || D1) {
#pragma unroll
                for (int q = 0; q < 4; q++) sm.As0[nxt][ak0 + 4 * q][ar] = pa0[q];
            }
            if (D2) {
#pragma unroll
                for (int q = 0; q < 4; q++) sm.As1[nxt][ak0 + 4 * q][ar] = pa1[q];
            }
#pragma unroll
            for (int q = 0; q < 3; q++) {
                if (D0) sm.Bs[0][nxt][bk][q * 16 + bc0] = pb0[q];
                if (D1) sm.Bs[1][nxt][bk][q * 16 + bc0] = pb1[q];
                if (D2) sm.Bs[2][nxt][bk][q * 16 + bc0] = pb2[q];
            }
        }
        __syncthreads();
    }
}

// ---------------- register-resident GRU cells --------------------------------------------------
// layer0: x-side is rank-1 (scalar xv per batch); acc0 = h0 x Whh0 (raw)
__device__ __forceinline__ void cell0_reg(Smem& sm, const u64* acc0, int src, int dst,
                                          int b0, int j0)
{
    const int tid = threadIdx.x;
    const int tr = tid & 15;
    const int tc = tid >> 4;
    const int j = j0 + tc;
    float hr[4], hz[4], hn[4];
    unpack2(hr[0], hr[1], acc0[0]); unpack2(hr[2], hr[3], acc0[1]);
    unpack2(hz[0], hz[1], acc0[2]); unpack2(hz[2], hz[3], acc0[3]);
    unpack2(hn[0], hn[1], acc0[4]); unpack2(hn[2], hn[3], acc0[5]);
    const float wr = sm.wih0[tc],     wz = sm.wih0[16 + tc],     wn = sm.wih0[32 + tc];
    const float br = sm.bih0s[tc],    bz = sm.bih0s[16 + tc],    bn = sm.bih0s[32 + tc];
    const float cr = sm.bhh0s[tc],    cz = sm.bhh0s[16 + tc],    cn = sm.bhh0s[32 + tc];
    float4 xvv = *reinterpret_cast<const float4*>(&sm.xv[4 * tr]);
    float4 hp  = *reinterpret_cast<const float4*>(&g_h0[src][j][b0 + 4 * tr]);
    const float xa[4] = {xvv.x, xvv.y, xvv.z, xvv.w};
    const float ha[4] = {hp.x, hp.y, hp.z, hp.w};
    float o[4];
#pragma unroll
    for (int i = 0; i < 4; i++) {
        float r = sigf(fmaf(xa[i], wr, br) + hr[i] + cr);
        float z = sigf(fmaf(xa[i], wz, bz) + hz[i] + cz);
        float n = tanh_f(fmaf(xa[i], wn, bn) + r * (hn[i] + cn));
        o[i] = (1.f - z) * n + z * ha[i];
    }
    *reinterpret_cast<float4*>(&g_h0[dst][j][b0 + 4 * tr]) = make_float4(o[0], o[1], o[2], o[3]);
}

// layer1: acc1 = y0 x Wih1 (raw), acc2 = h1 x Whh1 (raw); r multiplies only the hh side of n
__device__ __forceinline__ void cell1_reg(Smem& sm, const u64* acc1, const u64* acc2,
                                          int src, int dst, int b0, int j0)
{
    const int tid = threadIdx.x;
    const int tr = tid & 15;
    const int tc = tid >> 4;
    const int j = j0 + tc;
    float xr[4], xz[4], xn[4], hr[4], hz[4], hn[4];
    unpack2(xr[0], xr[1], acc1[0]); unpack2(xr[2], xr[3], acc1[1]);
    unpack2(xz[0], xz[1], acc1[2]); unpack2(xz[2], xz[3], acc1[3]);
    unpack2(xn[0], xn[1], acc1[4]); unpack2(xn[2], xn[3], acc1[5]);
    unpack2(hr[0], hr[1], acc2[0]); unpack2(hr[2], hr[3], acc2[1]);
    unpack2(hz[0], hz[1], acc2[2]); unpack2(hz[2], hz[3], acc2[3]);
    unpack2(hn[0], hn[1], acc2[4]); unpack2(hn[2], hn[3], acc2[5]);
    const float br = sm.bih1s[tc],  bz = sm.bih1s[16 + tc],  bn = sm.bih1s[32 + tc];
    const float cr = sm.bhh1s[tc],  cz = sm.bhh1s[16 + tc],  cn = sm.bhh1s[32 + tc];
    float4 hp = *reinterpret_cast<const float4*>(&g_h1[src][j][b0 + 4 * tr]);
    const float ha[4] = {hp.x, hp.y, hp.z, hp.w};
    float o[4];
#pragma unroll
    for (int i = 0; i < 4; i++) {
        float r = sigf(xr[i] + br + hr[i] + cr);
        float z = sigf(xz[i] + bz + hz[i] + cz);
        float n = tanh_f(xn[i] + bn + r * (hn[i] + cn));
        o[i] = (1.f - z) * n + z * ha[i];
    }
    *reinterpret_cast<float4*>(&g_h1[dst][j][b0 + 4 * tr]) = make_float4(o[0], o[1], o[2], o[3]);
}

// Per-block head over its 64-batch tile: xv[rr] = h1[:, b0+rr] . Wout + bout (= forecast/scale)
__device__ __forceinline__ void head_tile(const float* __restrict__ h1src, int b0,
                                          const float* __restrict__ Wout, float bout0,
                                          Smem& sm)
{
    const int tid = threadIdx.x;
    const int rr = tid >> 2;
    const int kq = tid & 3;
    float s = 0.f;
    const int kbase = kq * 128;
#pragma unroll 4
    for (int i = 0; i < 128; ++i) {
        int k = kbase + i;
        s = fmaf(__ldcg(&h1src[k * BB + b0 + rr]), __ldg(&Wout[k]), s);
    }
    s += __shfl_xor_sync(0xffffffffu, s, 1);
    s += __shfl_xor_sync(0xffffffffu, s, 2);
    if (kq == 0) sm.xv[rr] = s + bout0;
    __syncthreads();
}

// ---------------- kernel 1: init ---------------------------------------------------------------
__global__ void __launch_bounds__(NTHR)
k_init(const float* __restrict__ ctx)
{
    __shared__ float red[8];
    const int tid = threadIdx.x;
    const int bid = blockIdx.x;
    {
        const int total = 2 * HH * BB;
        float* z0 = &g_h0[0][0][0];
        float* z1 = &g_h1[0][0][0];
        for (int i = bid * NTHR + tid; i < total; i += GRID_X * NTHR) {
            z0[i] = 0.f;
            z1[i] = 0.f;
        }
    }
    const int b = 2 * bid + (tid >> 7);
    const int t = tid & 127;
    float s = 0.f;
#pragma unroll
    for (int q = 0; q < 4; q++) s += ctx[b * CTXL + t + 128 * q];
#pragma unroll
    for (int o = 16; o; o >>= 1) s += __shfl_xor_sync(0xffffffffu, s, o);
    if ((tid & 31) == 0) red[tid >> 5] = s;
    __syncthreads();
    if ((tid & 127) == 0) {
        int w0 = (tid >> 5);
        float m = (red[w0] + red[w0 + 1] + red[w0 + 2] + red[w0 + 3]) * (1.f / CTXL);
        float sc = fmaxf(fabsf(m), 1e-5f);
        g_scale[b] = sc;
        g_inv[b] = __fdividef(1.0f, sc);
    }
}

// ---------------- kernel 2: encoder phase p (layer0 step p + layer1 step p-1, fused) -----------
__global__ void __launch_bounds__(NTHR)
k_enc(const float* __restrict__ ctx,
      const float* __restrict__ Wih0, const float* __restrict__ Whh0,
      const float* __restrict__ bih0, const float* __restrict__ bhh0,
      const float* __restrict__ Wih1, const float* __restrict__ Whh1,
      const float* __restrict__ bih1, const float* __restrict__ bhh1,
      int p)
{
    __shared__ Smem sm;
    const int tid = threadIdx.x;
    const int bid = blockIdx.x;
    const int b0 = (bid >> 5) * 64;
    const int j0 = (bid & 31) * 16;
    const int src = (p + 1) & 1, dst = p & 1;

    if (tid < 48) {
        int g = (tid >> 4) * HH + j0 + (tid & 15);
        sm.wih0[tid]  = Wih0[g];
        sm.bih0s[tid] = bih0[g];
        sm.bhh0s[tid] = bhh0[g];
        sm.bih1s[tid] = bih1[g];
        sm.bhh1s[tid] = bhh1[g];
    }
    if (p < CTXL && tid < 64)
        sm.xv[tid] = ctx[(b0 + tid) * CTXL + p] * g_inv[b0 + tid];
    __syncthreads();

    u64 acc0[6] = {0, 0, 0, 0, 0, 0};
    u64 acc1[6] = {0, 0, 0, 0, 0, 0};
    u64 acc2[6] = {0, 0, 0, 0, 0, 0};
    fused_gemm<true, true, true>(sm, &g_h0[src][0][b0], &g_h1[src][0][b0],
                                 Whh0, Wih1, Whh1, j0, acc0, acc1, acc2);
    if (p < CTXL) cell0_reg(sm, acc0, src, dst, b0, j0);
    if (p >= 1)   cell1_reg(sm, acc1, acc2, src, dst, b0, j0);
}

// ---------------- kernel 3: decode layer0 (head on h1 -> out[d-1] + xv, then cell0) ------------
__global__ void __launch_bounds__(NTHR)
k_dec0(const float* __restrict__ Wih0, const float* __restrict__ Whh0,
       const float* __restrict__ bih0, const float* __restrict__ bhh0,
       const float* __restrict__ Wout, const float* __restrict__ bout,
       float* __restrict__ out, int d, int c0, int c1)
{
    __shared__ Smem sm;
    const int tid = threadIdx.x;
    const int bid = blockIdx.x;
    const int b0 = (bid >> 5) * 64;
    const int j0 = (bid & 31) * 16;

    if (tid < 48) {
        int g = (tid >> 4) * HH + j0 + (tid & 15);
        sm.wih0[tid]  = Wih0[g];
        sm.bih0s[tid] = bih0[g];
        sm.bhh0s[tid] = bhh0[g];
    }
    __syncthreads();

    head_tile(&g_h1[c1][0][0], b0, Wout, __ldg(&bout[0]), sm);
    if (j0 == 0 && (tid & 3) == 0) {
        int rr = tid >> 2;
        out[(b0 + rr) * PREDL + (d - 1)] = sm.xv[rr] * g_scale[b0 + rr];
    }
    __syncthreads();

    u64 acc0[6] = {0, 0, 0, 0, 0, 0};
    u64 dmy[6];
    fused_gemm<true, false, false>(sm, &g_h0[c0][0][b0], &g_h0[c0][0][b0],
                                   Whh0, Whh0, Whh0, j0, acc0, dmy, dmy);
    cell0_reg(sm, acc0, c0, c0 ^ 1, b0, j0);
}

// ---------------- kernel 4: decode layer1 ------------------------------------------------------
__global__ void __launch_bounds__(NTHR)
k_dec1(const float* __restrict__ Wih1, const float* __restrict__ Whh1,
       const float* __restrict__ bih1, const float* __restrict__ bhh1,
       int h0buf, int c1)
{
    __shared__ Smem sm;
    const int tid = threadIdx.x;
    const int bid = blockIdx.x;
    const int b0 = (bid >> 5) * 64;
    const int j0 = (bid & 31) * 16;

    if (tid < 48) {
        int g = (tid >> 4) * HH + j0 + (tid & 15);
        sm.bih1s[tid] = bih1[g];
        sm.bhh1s[tid] = bhh1[g];
    }
    __syncthreads();

    u64 acc1[6] = {0, 0, 0, 0, 0, 0};
    u64 acc2[6] = {0, 0, 0, 0, 0, 0};
    u64 dmy[6];
    fused_gemm<false, true, true>(sm, &g_h0[h0buf][0][b0], &g_h1[c1][0][b0],
                                  Wih1, Wih1, Whh1, j0, dmy, acc1, acc2);
    cell1_reg(sm, acc1, acc2, c1, c1 ^ 1, b0, j0);
}

// ---------------- kernel 5: final head ---------------------------------------------------------
__global__ void __launch_bounds__(NTHR)
k_head(const float* __restrict__ Wout, const float* __restrict__ bout,
       float* __restrict__ out, int c1)
{
    __shared__ Smem sm;
    const int tid = threadIdx.x;
    const int b0 = blockIdx.x * 64;
    head_tile(&g_h1[c1][0][0], b0, Wout, __ldg(&bout[0]), sm);
    if ((tid & 3) == 0) {
        int rr = tid >> 2;
        out[(b0 + rr) * PREDL + (PREDL - 1)] = sm.xv[rr] * g_scale[b0 + rr];
    }
}

extern "C" void kernel_launch(void* const* d_in, const int* in_sizes, int n_in,
                              void* d_out, int out_size)
{
    const float* ctx  = (const float*)d_in[0];
    const float* Wih0 = (const float*)d_in[1];
    const float* Whh0 = (const float*)d_in[2];
    const float* bih0 = (const float*)d_in[3];
    const float* bhh0 = (const float*)d_in[4];
    const float* Wih1 = (const float*)d_in[5];
    const float* Whh1 = (const float*)d_in[6];
    const float* bih1 = (const float*)d_in[7];
    const float* bhh1 = (const float*)d_in[8];
    const float* Wout = (const float*)d_in[9];
    const float* bout = (const float*)d_in[10];
    float* out = (float*)d_out;

    k_init<<<GRID_X, NTHR>>>(ctx);

    for (int p = 0; p <= CTXL; ++p)
        k_enc<<<GRID_X, NTHR>>>(ctx, Wih0, Whh0, bih0, bhh0,
                                Wih1, Whh1, bih1, bhh1, p);

    int c0 = 1, c1 = 0;
    for (int d = 1; d < PREDL; ++d) {
        k_dec0<<<GRID_X, NTHR>>>(Wih0, Whh0, bih0, bhh0, Wout, bout, out, d, c0, c1);
        c0 ^= 1;
        k_dec1<<<GRID_X, NTHR>>>(Wih1, Whh1, bih1, bhh1, c0, c1);
        c1 ^= 1;
    }
    k_head<<<4, NTHR>>>(Wout, bout, out, c1);
}